// round 3
// baseline (speedup 1.0000x reference)
#include <cuda_runtime.h>
#include <cuda_bf16.h>
#include <math_constants.h>

// Problem shapes (fixed by setup_inputs)
#define B_  32
#define C_  256
#define N_  1024   // num queries = H*W
#define M_  1024   // H*W

// Scratch (device globals: allocation-free)
__device__ float g_S[(size_t)B_ * N_ * M_];   // 128 MB scores
__device__ float g_cb[B_ * M_];               // colmax + log(colsum)
__device__ int   g_idx[B_ * N_];              // per-row argmax

// ---------------------------------------------------------------------------
// Kernel 1: S[b] = (Q [N,C] x src[b] [C,M]) * (1/16)
// Classic 128x128x8 SGEMM, 256 threads, 8x8 per-thread tile.
// ---------------------------------------------------------------------------
#define BM 128
#define BN 128
#define BK 8
#define TM 8
#define TN 8

__global__ __launch_bounds__(256, 2)
void gemm_kernel(const float* __restrict__ q, const float* __restrict__ src) {
    int b  = blockIdx.z;
    int n0 = blockIdx.y * BM;
    int m0 = blockIdx.x * BN;

    const float* A  = q;                                   // [N_, C_]
    const float* Bp = src + (size_t)b * C_ * M_;           // [C_, M_]
    float*       Sp = g_S + (size_t)b * N_ * M_;

    __shared__ float As[BK][BM];
    __shared__ float Bs[BK][BN];

    int tid = threadIdx.x;
    // A-tile loader: 128 rows x 8 cols, 2 float4 per row -> 256 float4
    int arow  = tid >> 1;            // 0..127
    int acol4 = (tid & 1) * 4;       // 0 or 4
    // B-tile loader: 8 rows x 128 cols -> 256 float4
    int brow  = tid >> 5;            // 0..7
    int bcol4 = (tid & 31) * 4;      // 0..124

    int tx = tid & 15;               // 0..15 (m direction)
    int ty = tid >> 4;               // 0..15 (n direction)

    float acc[TM][TN];
    #pragma unroll
    for (int i = 0; i < TM; i++)
        #pragma unroll
        for (int j = 0; j < TN; j++) acc[i][j] = 0.0f;

    for (int k0 = 0; k0 < C_; k0 += BK) {
        float4 av = *(const float4*)&A[(size_t)(n0 + arow) * C_ + k0 + acol4];
        As[acol4 + 0][arow] = av.x;
        As[acol4 + 1][arow] = av.y;
        As[acol4 + 2][arow] = av.z;
        As[acol4 + 3][arow] = av.w;
        *(float4*)&Bs[brow][bcol4] =
            *(const float4*)&Bp[(size_t)(k0 + brow) * M_ + m0 + bcol4];
        __syncthreads();

        #pragma unroll
        for (int k = 0; k < BK; k++) {
            float ar[TM], br[TN];
            #pragma unroll
            for (int i = 0; i < TM; i++) ar[i] = As[k][ty * TM + i];
            #pragma unroll
            for (int j = 0; j < TN; j++) br[j] = Bs[k][tx * TN + j];
            #pragma unroll
            for (int i = 0; i < TM; i++)
                #pragma unroll
                for (int j = 0; j < TN; j++) acc[i][j] += ar[i] * br[j];
        }
        __syncthreads();
    }

    const float inv_temp = 0.0625f;   // 1/sqrt(256)
    #pragma unroll
    for (int i = 0; i < TM; i++) {
        float* row = Sp + (size_t)(n0 + ty * TM + i) * M_ + m0 + tx * TN;
        #pragma unroll
        for (int j = 0; j < TN; j += 4) {
            float4 v;
            v.x = acc[i][j + 0] * inv_temp;
            v.y = acc[i][j + 1] * inv_temp;
            v.z = acc[i][j + 2] * inv_temp;
            v.w = acc[i][j + 3] * inv_temp;
            *(float4*)&row[j] = v;
        }
    }
}

// ---------------------------------------------------------------------------
// Kernel 2: per-column (over n) online log-sum-exp:
//   cb[b][m] = max_n S[b][n][m] + log( sum_n exp(S - max) )
// One thread per column; consecutive threads -> consecutive m (coalesced).
// ---------------------------------------------------------------------------
__global__ void colstat_kernel() {
    int b = blockIdx.y;
    int m = blockIdx.x * blockDim.x + threadIdx.x;
    const float* Sp = g_S + (size_t)b * N_ * M_;

    float mx = -CUDART_INF_F;
    float sm = 0.0f;
    #pragma unroll 4
    for (int n = 0; n < N_; n++) {
        float v = Sp[(size_t)n * M_ + m];
        if (v > mx) {
            sm = sm * __expf(mx - v) + 1.0f;
            mx = v;
        } else {
            sm += __expf(v - mx);
        }
    }
    g_cb[b * M_ + m] = mx + logf(sm);
}

// ---------------------------------------------------------------------------
// Kernel 3: per-row argmax of  L = 2*S[b][n][m] - cb[b][m].
// One warp per row; 8 warps per block.
// ---------------------------------------------------------------------------
__global__ void rowargmax_kernel() {
    int row  = blockIdx.x * 8 + (threadIdx.x >> 5);   // b*N_ + n
    int lane = threadIdx.x & 31;
    int b    = row >> 10;

    const float* Sp = g_S + (size_t)row * M_;
    const float* cb = g_cb + b * M_;

    float best = -CUDART_INF_F;
    int   bi   = 0;
    #pragma unroll 4
    for (int m = lane; m < M_; m += 32) {
        float L = 2.0f * Sp[m] - cb[m];
        if (L > best) { best = L; bi = m; }
    }
    #pragma unroll
    for (int off = 16; off > 0; off >>= 1) {
        float ob = __shfl_down_sync(0xffffffffu, best, off);
        int   oi = __shfl_down_sync(0xffffffffu, bi, off);
        if (ob > best || (ob == best && oi < bi)) { best = ob; bi = oi; }
    }
    if (lane == 0) g_idx[row] = bi;
}

// ---------------------------------------------------------------------------
// Kernel 4: gather.  out[b][c][n] = src[b][c][ idx[b][n] ]
// Block per (b,c): stage the 4KB src row + 4KB idx row in smem.
// ---------------------------------------------------------------------------
__global__ void gather_kernel(const float* __restrict__ src, float* __restrict__ out) {
    __shared__ float row[M_];
    __shared__ int   sidx[N_];
    int b = blockIdx.y;
    int c = blockIdx.x;
    const float* sr = src + ((size_t)b * C_ + c) * M_;
    const int*   ip = g_idx + b * N_;
    float*       op = out + ((size_t)b * C_ + c) * N_;

    int t = threadIdx.x;
    for (int i = t; i < M_; i += blockDim.x) {
        row[i]  = sr[i];
        sidx[i] = ip[i];
    }
    __syncthreads();
    for (int i = t; i < N_; i += blockDim.x)
        op[i] = row[sidx[i]];
}

// ---------------------------------------------------------------------------
extern "C" void kernel_launch(void* const* d_in, const int* in_sizes, int n_in,
                              void* d_out, int out_size) {
    const float* src = (const float*)d_in[0];   // [B, C, H, W] = [32,256,32,32]
    const float* qw  = (const float*)d_in[1];   // [N, C]       = [1024,256]
    float* out = (float*)d_out;                 // [B, C, H, W]

    (void)in_sizes; (void)n_in; (void)out_size;

    dim3 ggrid(M_ / BN, N_ / BM, B_);           // (8, 8, 32)
    gemm_kernel<<<ggrid, 256>>>(qw, src);

    dim3 cgrid(M_ / 128, B_);                   // (8, 32)
    colstat_kernel<<<cgrid, 128>>>();

    rowargmax_kernel<<<(B_ * N_) / 8, 256>>>();

    dim3 ogrid(C_, B_);                         // (256, 32)
    gather_kernel<<<ogrid, 256>>>(src, out);
}

// round 6
// speedup vs baseline: 3.1192x; 3.1192x over previous
#include <cuda_runtime.h>
#include <cuda_fp16.h>
#include <cstdint>
#include <math_constants.h>

// Shapes (fixed by setup_inputs)
#define B_  32
#define C_  256
#define N_  1024
#define M_  1024

// ---------------------------------------------------------------------------
// Device scratch (allocation-free)
// ---------------------------------------------------------------------------
__device__ float  g_S[(size_t)B_ * N_ * M_];          // 128 MB scores
__device__ __half g_Qs[2][N_ * C_];                   // (Q/16) fp16 limbs [n][c]
__device__ __half g_Ks[2][(size_t)B_ * M_ * C_];      // src fp16 limbs, [b][m][c]
__device__ float2 g_cpart[B_][8][M_];                 // per-n-strip col partials (max,sum)
__device__ float  g_cb[B_ * M_];                      // colmax + log(colsum)
__device__ int    g_idx[B_ * N_];                     // per-row argmax

__device__ __forceinline__ void split2(float v, __half& h, __half& m) {
    h = __float2half(v);
    m = __float2half(v - __half2float(h));
}

// ---------------------------------------------------------------------------
// PTX helpers (sm_80-era: valid on base sm_100 target)
// ---------------------------------------------------------------------------
__device__ __forceinline__ uint32_t smem_u32(const void* p) {
    uint32_t a;
    asm("{ .reg .u64 t; cvta.to.shared.u64 t, %1; cvt.u32.u64 %0, t; }" : "=r"(a) : "l"(p));
    return a;
}
#define CP_ASYNC16(saddr, gaddr) \
    asm volatile("cp.async.cg.shared.global [%0], [%1], 16;" \
                 :: "r"(saddr), "l"(gaddr) : "memory")
#define CP_COMMIT()  asm volatile("cp.async.commit_group;" ::: "memory")
#define CP_WAIT(n)   asm volatile("cp.async.wait_group %0;" :: "n"(n) : "memory")

#define LDMATRIX_X4(r0, r1, r2, r3, addr) \
    asm volatile("ldmatrix.sync.aligned.m8n8.x4.shared.b16 {%0,%1,%2,%3}, [%4];" \
                 : "=r"(r0), "=r"(r1), "=r"(r2), "=r"(r3) : "r"(addr))

__device__ __forceinline__ void mma16816(float* d, const uint32_t* a, const uint32_t* b) {
    asm volatile(
        "mma.sync.aligned.m16n8k16.row.col.f32.f16.f16.f32 "
        "{%0,%1,%2,%3}, {%4,%5,%6,%7}, {%8,%9}, {%0,%1,%2,%3};"
        : "+f"(d[0]), "+f"(d[1]), "+f"(d[2]), "+f"(d[3])
        : "r"(a[0]), "r"(a[1]), "r"(a[2]), "r"(a[3]), "r"(b[0]), "r"(b[1]));
}

// ---------------------------------------------------------------------------
// Kernel 0a: split Q (temperature 1/16 folded in)
// ---------------------------------------------------------------------------
__global__ void split_q_kernel(const float* __restrict__ qw) {
    int i = blockIdx.x * 256 + threadIdx.x;
    float v = qw[i] * 0.0625f;
    __half h, m;
    split2(v, h, m);
    g_Qs[0][i] = h; g_Qs[1][i] = m;
}

// ---------------------------------------------------------------------------
// Kernel 0b: split + transpose src [b][c][m] -> [b][m][c]
// ---------------------------------------------------------------------------
__global__ void split_k_kernel(const float* __restrict__ src) {
    __shared__ float tile[32][33];
    int b = blockIdx.z, c0 = blockIdx.y * 32, m0 = blockIdx.x * 32;
    int t = threadIdx.x, tx = t & 31, ty = t >> 5;
    const float* sp = src + (size_t)b * C_ * M_;
    #pragma unroll
    for (int i = 0; i < 4; i++) {
        int c = c0 + ty + i * 8;
        tile[ty + i * 8][tx] = sp[(size_t)c * M_ + m0 + tx];
    }
    __syncthreads();
    #pragma unroll
    for (int i = 0; i < 4; i++) {
        int m = m0 + ty + i * 8;
        float v = tile[tx][ty + i * 8];
        __half h, mm;
        split2(v, h, mm);
        size_t o = ((size_t)b * M_ + m) * C_ + c0 + tx;
        g_Ks[0][o] = h; g_Ks[1][o] = mm;
    }
}

// ---------------------------------------------------------------------------
// Kernel 1: fp16x3 HMMA GEMM.  S[b][n][m] = sum_c (q[n][c]/16) * src[b][c][m]
//   limb products: hh, hm, mh  (mm and l-terms dropped: ~5e-7 on s~N(0,1))
// CTA 128n x 128m, 8 warps (4n x 2m), warp tile 32n x 64m.
// K: 3 limb segments x 256, chunks of 32, double-buffered cp.async.
// Smem tiles: 128 rows x 32 fp16 (64B rows), 16B units XOR-swizzled by (row>>1)&3.
// Fused epilogue: per-column (over this CTA's 128 n-rows) max + sumexp partials.
// ---------------------------------------------------------------------------
#define KC 32
#define NITER 24    // 3 segs * 8 chunks

struct SmemTiles {
    char   A[2][128 * 64];   // 8 KB each
    char   B[2][128 * 64];
    float2 cstats[4][128];   // per-warp-row-strip column stats
};

__device__ __forceinline__ uint32_t sw_addr(uint32_t base, int row, int unit) {
    return base + row * 64 + ((unit ^ ((row >> 1) & 3)) << 4);
}

__global__ __launch_bounds__(256)
void gemm_fp16x3_kernel() {
    __shared__ SmemTiles sm;
    const uint32_t sbA[2] = { smem_u32(sm.A[0]), smem_u32(sm.A[1]) };
    const uint32_t sbB[2] = { smem_u32(sm.B[0]), smem_u32(sm.B[1]) };

    int tid = threadIdx.x;
    int wid = tid >> 5, lid = tid & 31;
    int wn = wid >> 1, wm = wid & 1;            // 4 x 2 warp grid

    int m0 = blockIdx.x * 128;
    int n0 = blockIdx.y * 128;
    int b  = blockIdx.z;

    // limb product table: hh, hm, mh
    const int sa_tab[3] = {0, 0, 1};
    const int sb_tab[3] = {0, 1, 0};

    // loader: each thread handles 2 x 16B units for A and for B per chunk
    int lrow[2], lunit[2];
    #pragma unroll
    for (int t = 0; t < 2; t++) {
        int idx = tid + t * 256;                // 0..511
        lrow[t] = idx >> 2; lunit[t] = idx & 3;
    }

    auto load_chunk = [&](int buf, int it) {
        int seg = it >> 3, kc = (it & 7) * KC;
        const __half* gA = g_Qs[sa_tab[seg]] + (size_t)n0 * C_ + kc;
        const __half* gB = g_Ks[sb_tab[seg]] + ((size_t)b * M_ + m0) * C_ + kc;
        #pragma unroll
        for (int t = 0; t < 2; t++) {
            int row = lrow[t], u = lunit[t];
            CP_ASYNC16(sw_addr(sbA[buf], row, u), gA + (size_t)row * C_ + u * 8);
        }
        #pragma unroll
        for (int t = 0; t < 2; t++) {
            int row = lrow[t], u = lunit[t];
            CP_ASYNC16(sw_addr(sbB[buf], row, u), gB + (size_t)row * C_ + u * 8);
        }
        CP_COMMIT();
    };

    float acc[2][8][4];
    #pragma unroll
    for (int i = 0; i < 2; i++)
        #pragma unroll
        for (int j = 0; j < 8; j++)
            #pragma unroll
            for (int c = 0; c < 4; c++) acc[i][j][c] = 0.0f;

    load_chunk(0, 0);

    for (int it = 0; it < NITER; it++) {
        __syncthreads();                         // buffer (it+1)&1 free to overwrite
        if (it + 1 < NITER) {
            load_chunk((it + 1) & 1, it + 1);
            CP_WAIT(1);
        } else {
            CP_WAIT(0);
        }
        __syncthreads();                         // chunk `it` visible to all

        uint32_t Ab = sbA[it & 1], Bb = sbB[it & 1];
        int tile = lid >> 3, trow = lid & 7;

        #pragma unroll
        for (int ks = 0; ks < 2; ks++) {
            // A fragments: 2 m16 tiles (rows wn*32 + i*16 .. +15, k ks*16..+15)
            uint32_t aF[2][4];
            #pragma unroll
            for (int i = 0; i < 2; i++) {
                int row = wn * 32 + i * 16 + (tile & 1) * 8 + trow;
                int unit = 2 * ks + (tile >> 1);
                LDMATRIX_X4(aF[i][0], aF[i][1], aF[i][2], aF[i][3],
                            sw_addr(Ab, row, unit));
            }
            // B fragments: 8 n8 tiles
            uint32_t bF[8][2];
            #pragma unroll
            for (int p = 0; p < 4; p++) {
                int row = wm * 64 + p * 16 + (tile >> 1) * 8 + trow;
                int unit = 2 * ks + (tile & 1);
                uint32_t r0, r1, r2, r3;
                LDMATRIX_X4(r0, r1, r2, r3, sw_addr(Bb, row, unit));
                bF[2 * p][0] = r0;     bF[2 * p][1] = r1;
                bF[2 * p + 1][0] = r2; bF[2 * p + 1][1] = r3;
            }
            #pragma unroll
            for (int i = 0; i < 2; i++)
                #pragma unroll
                for (int j = 0; j < 8; j++)
                    mma16816(acc[i][j], aF[i], bF[j]);
        }
    }

    // ---- Epilogue 1: write S ----
    // fragment layout: d0,d1 @ (r_in, c_in..+1); d2,d3 @ (r_in+8, c_in..+1)
    int r_in = lid >> 2, c_in = (lid & 3) * 2;
    #pragma unroll
    for (int i = 0; i < 2; i++) {
        #pragma unroll
        for (int j = 0; j < 8; j++) {
            int gr = n0 + wn * 32 + i * 16 + r_in;
            int gc = m0 + wm * 64 + j * 8 + c_in;
            float* p0 = g_S + ((size_t)b * N_ + gr) * M_ + gc;
            float* p1 = p0 + 8 * M_;
            *(float2*)p0 = make_float2(acc[i][j][0], acc[i][j][1]);
            *(float2*)p1 = make_float2(acc[i][j][2], acc[i][j][3]);
        }
    }

    // ---- Epilogue 2: column (over n) max + sumexp partials ----
    // Lanes with equal (lid&3) own the same 2 columns; butterfly over strides 4,8,16.
    #pragma unroll
    for (int j = 0; j < 8; j++) {
        #pragma unroll
        for (int o = 0; o < 2; o++) {
            float v0 = acc[0][j][o], v1 = acc[0][j][o + 2];
            float v2 = acc[1][j][o], v3 = acc[1][j][o + 2];
            float mx = fmaxf(fmaxf(v0, v1), fmaxf(v2, v3));
            #pragma unroll
            for (int off = 4; off <= 16; off <<= 1)
                mx = fmaxf(mx, __shfl_xor_sync(0xffffffffu, mx, off));
            float sum = __expf(v0 - mx) + __expf(v1 - mx)
                      + __expf(v2 - mx) + __expf(v3 - mx);
            #pragma unroll
            for (int off = 4; off <= 16; off <<= 1)
                sum += __shfl_xor_sync(0xffffffffu, sum, off);
            if (lid < 4)
                sm.cstats[wn][wm * 64 + j * 8 + lid * 2 + o] = make_float2(mx, sum);
        }
    }
    __syncthreads();
    if (tid < 128) {
        float gm = -CUDART_INF_F, gs = 0.0f;
        #pragma unroll
        for (int w = 0; w < 4; w++) {
            float2 p = sm.cstats[w][tid];
            if (p.x > gm) { gs = gs * __expf(gm - p.x) + p.y; gm = p.x; }
            else          { gs += p.y * __expf(p.x - gm); }
        }
        g_cpart[b][blockIdx.y][m0 + tid] = make_float2(gm, gs);
    }
}

// ---------------------------------------------------------------------------
// Kernel 2: combine 8 n-strip partials -> cb[b][m] = colmax + log(colsum)
// ---------------------------------------------------------------------------
__global__ void reduce_cb_kernel() {
    int b = blockIdx.y;
    int m = blockIdx.x * 256 + threadIdx.x;
    float gm = -CUDART_INF_F, gs = 0.0f;
    #pragma unroll
    for (int s = 0; s < 8; s++) {
        float2 p = g_cpart[b][s][m];
        if (p.x > gm) { gs = gs * __expf(gm - p.x) + p.y; gm = p.x; }
        else          { gs += p.y * __expf(p.x - gm); }
    }
    g_cb[b * M_ + m] = gm + logf(gs);
}

// ---------------------------------------------------------------------------
// Kernel 3: per-row argmax of  L = 2*S - cb.  One warp per row.
// ---------------------------------------------------------------------------
__global__ void rowargmax_kernel() {
    int row  = blockIdx.x * 8 + (threadIdx.x >> 5);
    int lane = threadIdx.x & 31;
    int b    = row >> 10;
    const float* Sp = g_S + (size_t)row * M_;
    const float* cb = g_cb + b * M_;

    float best = -CUDART_INF_F; int bi = 0;
    #pragma unroll 4
    for (int m = lane; m < M_; m += 32) {
        float L = 2.0f * Sp[m] - cb[m];
        if (L > best) { best = L; bi = m; }
    }
    #pragma unroll
    for (int off = 16; off > 0; off >>= 1) {
        float ob = __shfl_down_sync(0xffffffffu, best, off);
        int   oi = __shfl_down_sync(0xffffffffu, bi, off);
        if (ob > best || (ob == best && oi < bi)) { best = ob; bi = oi; }
    }
    if (lane == 0) g_idx[row] = bi;
}

// ---------------------------------------------------------------------------
// Kernel 4: gather.  out[b][c][n] = src[b][c][ idx[b][n] ]
// ---------------------------------------------------------------------------
__global__ void gather_kernel(const float* __restrict__ src, float* __restrict__ out) {
    __shared__ float row[M_];
    __shared__ int   sidx[N_];
    int b = blockIdx.y, c = blockIdx.x;
    const float* sr = src + ((size_t)b * C_ + c) * M_;
    const int*   ip = g_idx + b * N_;
    float*       op = out + ((size_t)b * C_ + c) * N_;
    int t = threadIdx.x;
    for (int i = t; i < M_; i += blockDim.x) { row[i] = sr[i]; sidx[i] = ip[i]; }
    __syncthreads();
    for (int i = t; i < N_; i += blockDim.x) op[i] = row[sidx[i]];
}

// ---------------------------------------------------------------------------
extern "C" void kernel_launch(void* const* d_in, const int* in_sizes, int n_in,
                              void* d_out, int out_size) {
    const float* src = (const float*)d_in[0];   // [32,256,32,32]
    const float* qw  = (const float*)d_in[1];   // [1024,256]
    float* out = (float*)d_out;
    (void)in_sizes; (void)n_in; (void)out_size;

    split_q_kernel<<<N_ * C_ / 256, 256>>>(qw);
    split_k_kernel<<<dim3(M_ / 32, C_ / 32, B_), 256>>>(src);

    gemm_fp16x3_kernel<<<dim3(M_ / 128, N_ / 128, B_), 256>>>();

    reduce_cb_kernel<<<dim3(M_ / 256, B_), 256>>>();
    rowargmax_kernel<<<(B_ * N_) / 8, 256>>>();
    gather_kernel<<<dim3(C_, B_), 256>>>(src, out);
}